// round 7
// baseline (speedup 1.0000x reference)
#include <cuda_runtime.h>
#include <cuda_fp16.h>
#include <cstdint>

#define DD 64
#define NMAX 100032
#define NRELMAX 256
#define EMAX 2000000
#define BN 128   // nodes per block in k_tables

// bit-cast helpers
__device__ __forceinline__ unsigned h2_as_u32(__half2 h) {
    union { __half2 h; unsigned u; } c; c.h = h; return c.u;
}
__device__ __forceinline__ __half2 u32_as_h2(unsigned u) {
    union { unsigned u; __half2 h; } c; c.u = u; return c.h;
}

// packed f32x2 helpers (Blackwell; ptxas never auto-fuses these)
__device__ __forceinline__ void fma2(unsigned long long& acc, unsigned long long a,
                                     unsigned long long b) {
    asm("fma.rn.f32x2 %0, %1, %2, %0;" : "+l"(acc) : "l"(a), "l"(b));
}
__device__ __forceinline__ unsigned long long bcast2(float x) {
    unsigned long long r;
    asm("mov.b64 %0, {%1, %1};" : "=l"(r) : "f"(x));
    return r;
}
__device__ __forceinline__ float2 unpack2(unsigned long long v) {
    float2 f;
    asm("mov.b64 {%0, %1}, %2;" : "=f"(f.x), "=f"(f.y) : "l"(v));
    return f;
}

// Static scratch
// per node: 64 dims x half2{GE, M} = 256 B = 16 uint4
__device__ uint4 g_comb[(size_t)NMAX * 16];
__device__ float g_eg2[NRELMAX * DD];
__device__ int   g_count[NMAX];
__device__ int   g_rowstart[NMAX + 1];
__device__ int   g_cursor[NMAX];
__device__ int   g_bsum[1024];
__device__ unsigned g_csr[EMAX];                      // packed (s<<8)|t

// ---------------------------------------------------------------------------
// init: zero degree counters + EG2 = exp(E_gate)   (merged launch)
// ---------------------------------------------------------------------------
__global__ void k_init(const float* __restrict__ Eg, int n, int relTotal) {
    int i = blockIdx.x * blockDim.x + threadIdx.x;
    if (i < n) g_count[i] = 0;
    if (i < relTotal) g_eg2[i] = __expf(Eg[i]);
}

// ---------------------------------------------------------------------------
// per-node tables, register-tiled, packed f32x2 FMA inner loop.
//   M = relu(x@Vp+Bm); GE = exp(x@Vg+Bgp); store half2{GE, M} per dim.
// ---------------------------------------------------------------------------
__global__ void __launch_bounds__(256, 2) k_tables(
    const float* __restrict__ X, const float* __restrict__ Vp,
    const float* __restrict__ Vg, const float* __restrict__ Bm,
    const float* __restrict__ Bg, int n)
{
    __shared__ float sX[BN][DD];   // 32 KB
    int tid = threadIdx.x;
    int nodeBase = blockIdx.x * BN;

    {
        float4* s4 = reinterpret_cast<float4*>(&sX[0][0]);
        const float4* g4 = reinterpret_cast<const float4*>(X);
        for (int i = tid; i < BN * (DD / 4); i += 256) {
            int node = i >> 4;
            float4 v = make_float4(0.f, 0.f, 0.f, 0.f);
            if (nodeBase + node < n) v = __ldg(g4 + (size_t)(nodeBase + node) * (DD / 4) + (i & 15));
            s4[i] = v;
        }
    }
    __syncthreads();

    int dg = tid & 15, ng = tid >> 4;
    int d0 = dg * 4, n0 = ng * 8;

    // accumulators as packed f32x2 pairs: [node][pair]  (pair0 = dims d0,d0+1)
    unsigned long long accP[8][2], accG[8][2];
#pragma unroll
    for (int i = 0; i < 8; i++) {
        accP[i][0] = 0ull; accP[i][1] = 0ull;
        accG[i][0] = 0ull; accG[i][1] = 0ull;
    }

#pragma unroll 8
    for (int k = 0; k < DD; k++) {
        ulonglong2 p = __ldg(reinterpret_cast<const ulonglong2*>(Vp + k * DD + d0));
        ulonglong2 g = __ldg(reinterpret_cast<const ulonglong2*>(Vg + k * DD + d0));
#pragma unroll
        for (int i = 0; i < 8; i++) {
            unsigned long long xx = bcast2(sX[n0 + i][k]);
            fma2(accP[i][0], xx, p.x);
            fma2(accP[i][1], xx, p.y);
            fma2(accG[i][0], xx, g.x);
            fma2(accG[i][1], xx, g.y);
        }
    }

    float4 bm = __ldg(reinterpret_cast<const float4*>(Bm + d0));
    float4 bg = __ldg(reinterpret_cast<const float4*>(Bg + d0));

#pragma unroll
    for (int i = 0; i < 8; i++) {
        int gnode = nodeBase + n0 + i;
        if (gnode >= n) break;
        float2 p01 = unpack2(accP[i][0]);
        float2 p23 = unpack2(accP[i][1]);
        float2 g01 = unpack2(accG[i][0]);
        float2 g23 = unpack2(accG[i][1]);
        float m0 = fmaxf(p01.x + bm.x, 0.f);
        float m1 = fmaxf(p01.y + bm.y, 0.f);
        float m2 = fmaxf(p23.x + bm.z, 0.f);
        float m3 = fmaxf(p23.y + bm.w, 0.f);
        float e0 = __expf(g01.x + bg.x);
        float e1 = __expf(g01.y + bg.y);
        float e2 = __expf(g23.x + bg.z);
        float e3 = __expf(g23.y + bg.w);
        uint4 v;
        v.x = h2_as_u32(__floats2half2_rn(e0, m0));   // low=GE, high=M
        v.y = h2_as_u32(__floats2half2_rn(e1, m1));
        v.z = h2_as_u32(__floats2half2_rn(e2, m2));
        v.w = h2_as_u32(__floats2half2_rn(e3, m3));
        g_comb[(size_t)gnode * 16 + dg] = v;
    }
}

// ---------------------------------------------------------------------------
// CSR build: histogram -> scan (3 kernels) -> scatter
// ---------------------------------------------------------------------------
__global__ void k_hist(const int* __restrict__ ridx, int E) {
    int i = blockIdx.x * blockDim.x + threadIdx.x;
    if (i < E) atomicAdd(&g_count[__ldg(ridx + i)], 1);
}

__global__ void __launch_bounds__(1024) k_scan1(int n) {
    __shared__ int sd[1024];
    int tid = threadIdx.x;
    int i = blockIdx.x * 1024 + tid;
    sd[tid] = (i < n) ? g_count[i] : 0;
    __syncthreads();
#pragma unroll
    for (int s = 512; s > 0; s >>= 1) {
        if (tid < s) sd[tid] += sd[tid + s];
        __syncthreads();
    }
    if (tid == 0) g_bsum[blockIdx.x] = sd[0];
}

__global__ void __launch_bounds__(1024) k_scan2(int nb, int n) {
    __shared__ int sd[1024];
    int tid = threadIdx.x;
    int v = (tid < nb) ? g_bsum[tid] : 0;
    sd[tid] = v;
    __syncthreads();
#pragma unroll
    for (int d = 1; d < 1024; d <<= 1) {
        int t = (tid >= d) ? sd[tid - d] : 0;
        __syncthreads();
        sd[tid] += t;
        __syncthreads();
    }
    if (tid < nb) g_bsum[tid] = sd[tid] - v;   // exclusive
    if (tid == 1023) g_rowstart[n] = sd[1023]; // total
}

__global__ void __launch_bounds__(1024) k_scan3(int n) {
    __shared__ int sd[1024];
    int tid = threadIdx.x;
    int i = blockIdx.x * 1024 + tid;
    int v = (i < n) ? g_count[i] : 0;
    sd[tid] = v;
    __syncthreads();
#pragma unroll
    for (int d = 1; d < 1024; d <<= 1) {
        int t = (tid >= d) ? sd[tid - d] : 0;
        __syncthreads();
        sd[tid] += t;
        __syncthreads();
    }
    if (i < n) {
        int excl = sd[tid] - v + g_bsum[blockIdx.x];
        g_rowstart[i] = excl;
        g_cursor[i] = excl;
    }
}

__global__ void k_scatter(const int* __restrict__ sidx, const int* __restrict__ ridx,
                          const int* __restrict__ tidx, int E) {
    int i = blockIdx.x * blockDim.x + threadIdx.x;
    if (i < E) {
        int r = __ldg(ridx + i);
        int pos = atomicAdd(&g_cursor[r], 1);
        g_csr[pos] = ((unsigned)__ldg(sidx + i) << 8) | (unsigned)__ldg(tidx + i);
    }
}

// ---------------------------------------------------------------------------
// Accumulate: one 16-lane group per receiver. fp16 gather (16 B/lane/edge),
// fp32 accumulation. t = GE*eg; den += t; num += M*t  (GE rounding cancels
// in num/den for dominant edges). Writes out directly; no atomics, no k_div.
// ---------------------------------------------------------------------------
__global__ void __launch_bounds__(256) k_accum(float* __restrict__ out, int n) {
    int gid = (blockIdx.x * 256 + threadIdx.x) >> 4;   // receiver
    if (gid >= n) return;                               // group-uniform
    int lane = threadIdx.x & 15;
    int gbase = (threadIdx.x & 31) & ~15;
    unsigned mask = 0xFFFFu << gbase;

    int beg = __ldg(&g_rowstart[gid]);
    int end = __ldg(&g_rowstart[gid + 1]);

    float4 num = make_float4(0.f, 0.f, 0.f, 0.f);
    float4 den = make_float4(0.f, 0.f, 0.f, 0.f);

    for (int chunk = beg; chunk < end; chunk += 16) {
        int m = end - chunk; if (m > 16) m = 16;
        unsigned pk = 0;
        if (chunk + lane < end) pk = __ldg(&g_csr[chunk + lane]);
        for (int j = 0; j < m; j++) {
            unsigned p = __shfl_sync(mask, pk, gbase + j);
            int s = p >> 8;
            int t = p & 255;
            uint4 raw = __ldg(&g_comb[(size_t)s * 16 + lane]);
            float4 g = __ldg(reinterpret_cast<const float4*>(g_eg2 + t * DD) + lane);
            float2 f0 = __half22float2(u32_as_h2(raw.x));  // {GE0, M0}
            float2 f1 = __half22float2(u32_as_h2(raw.y));
            float2 f2 = __half22float2(u32_as_h2(raw.z));
            float2 f3 = __half22float2(u32_as_h2(raw.w));
            float t0 = f0.x * g.x;  den.x += t0;  num.x = fmaf(f0.y, t0, num.x);
            float t1 = f1.x * g.y;  den.y += t1;  num.y = fmaf(f1.y, t1, num.y);
            float t2 = f2.x * g.z;  den.z += t2;  num.z = fmaf(f2.y, t2, num.z);
            float t3 = f3.x * g.w;  den.w += t3;  num.w = fmaf(f3.y, t3, num.w);
        }
    }

    float4 o;
    o.x = den.x > 0.f ? num.x / den.x : 0.f;
    o.y = den.y > 0.f ? num.y / den.y : 0.f;
    o.z = den.z > 0.f ? num.z / den.z : 0.f;
    o.w = den.w > 0.f ? num.w / den.w : 0.f;
    *(reinterpret_cast<float4*>(out + (size_t)gid * DD) + lane) = o;
}

// ---------------------------------------------------------------------------
extern "C" void kernel_launch(void* const* d_in, const int* in_sizes, int n_in,
                              void* d_out, int out_size)
{
    const float* X   = (const float*)d_in[0];
    const float* Vp  = (const float*)d_in[1];
    const float* Vg  = (const float*)d_in[2];
    const float* Eg  = (const float*)d_in[3];
    const float* Bm  = (const float*)d_in[4];
    const float* Bg  = (const float*)d_in[5];
    const int* sidx  = (const int*)d_in[6];
    const int* ridx  = (const int*)d_in[7];
    const int* tidx  = (const int*)d_in[8];
    float* out = (float*)d_out;

    int n        = in_sizes[0] / DD;
    int E        = in_sizes[6];
    int relTotal = in_sizes[3];
    int nb       = (n + 1023) / 1024;

    k_init<<<(n + 255) / 256, 256>>>(Eg, n, relTotal);
    k_tables<<<(n + BN - 1) / BN, 256>>>(X, Vp, Vg, Bm, Bg, n);

    k_hist<<<(E + 255) / 256, 256>>>(ridx, E);
    k_scan1<<<nb, 1024>>>(n);
    k_scan2<<<1, 1024>>>(nb, n);
    k_scan3<<<nb, 1024>>>(n);
    k_scatter<<<(E + 255) / 256, 256>>>(sidx, ridx, tidx, E);

    long long work = (long long)n * 16;
    k_accum<<<(int)((work + 255) / 256), 256>>>(out, n);
}

// round 8
// speedup vs baseline: 1.0097x; 1.0097x over previous
#include <cuda_runtime.h>
#include <cuda_fp16.h>
#include <cstdint>

#define DD 64
#define NMAX 100032
#define NRELMAX 256
#define EMAX 2000000
#define BN 128   // nodes per block in k_tables

// bit-cast helpers
__device__ __forceinline__ unsigned h2_as_u32(__half2 h) {
    union { __half2 h; unsigned u; } c; c.h = h; return c.u;
}
__device__ __forceinline__ __half2 u32_as_h2(unsigned u) {
    union { unsigned u; __half2 h; } c; c.u = u; return c.h;
}

// Static scratch
// per node: 64 dims x half2{GE, M} = 256 B = 16 uint4
__device__ uint4 g_comb[(size_t)NMAX * 16];
__device__ float g_eg2[NRELMAX * DD];
__device__ int   g_count[NMAX];
__device__ int   g_rowstart[NMAX + 1];
__device__ int   g_cursor[NMAX];
__device__ int   g_bsum[1024];
__device__ unsigned g_csr[EMAX];                      // packed (s<<8)|t

// ---------------------------------------------------------------------------
// init: zero degree counters + EG2 = exp(E_gate)   (merged launch)
// ---------------------------------------------------------------------------
__global__ void k_init(const float* __restrict__ Eg, int n, int relTotal) {
    int i = blockIdx.x * blockDim.x + threadIdx.x;
    if (i < n) g_count[i] = 0;
    if (i < relTotal) g_eg2[i] = __expf(Eg[i]);
}

// ---------------------------------------------------------------------------
// per-node tables, register-tiled (FFMA version — R6 baseline).
//   M = relu(x@Vp+Bm); GE = exp(x@Vg+Bgp); store half2{GE, M} per dim.
// ---------------------------------------------------------------------------
__global__ void __launch_bounds__(256, 2) k_tables(
    const float* __restrict__ X, const float* __restrict__ Vp,
    const float* __restrict__ Vg, const float* __restrict__ Bm,
    const float* __restrict__ Bg, int n)
{
    __shared__ float sX[BN][DD];   // 32 KB
    int tid = threadIdx.x;
    int nodeBase = blockIdx.x * BN;

    {
        float4* s4 = reinterpret_cast<float4*>(&sX[0][0]);
        const float4* g4 = reinterpret_cast<const float4*>(X);
        for (int i = tid; i < BN * (DD / 4); i += 256) {
            int node = i >> 4;
            float4 v = make_float4(0.f, 0.f, 0.f, 0.f);
            if (nodeBase + node < n) v = __ldg(g4 + (size_t)(nodeBase + node) * (DD / 4) + (i & 15));
            s4[i] = v;
        }
    }
    __syncthreads();

    int dg = tid & 15, ng = tid >> 4;
    int d0 = dg * 4, n0 = ng * 8;

    float accP[8][4], accG[8][4];
#pragma unroll
    for (int i = 0; i < 8; i++)
#pragma unroll
        for (int j = 0; j < 4; j++) { accP[i][j] = 0.f; accG[i][j] = 0.f; }

#pragma unroll 8
    for (int k = 0; k < DD; k++) {
        float4 p = __ldg(reinterpret_cast<const float4*>(Vp + k * DD + d0));
        float4 g = __ldg(reinterpret_cast<const float4*>(Vg + k * DD + d0));
        float xs[8];
#pragma unroll
        for (int i = 0; i < 8; i++) xs[i] = sX[n0 + i][k];
#pragma unroll
        for (int i = 0; i < 8; i++) {
            float x = xs[i];
            accP[i][0] = fmaf(x, p.x, accP[i][0]);
            accP[i][1] = fmaf(x, p.y, accP[i][1]);
            accP[i][2] = fmaf(x, p.z, accP[i][2]);
            accP[i][3] = fmaf(x, p.w, accP[i][3]);
            accG[i][0] = fmaf(x, g.x, accG[i][0]);
            accG[i][1] = fmaf(x, g.y, accG[i][1]);
            accG[i][2] = fmaf(x, g.z, accG[i][2]);
            accG[i][3] = fmaf(x, g.w, accG[i][3]);
        }
    }

    float4 bm = __ldg(reinterpret_cast<const float4*>(Bm + d0));
    float4 bg = __ldg(reinterpret_cast<const float4*>(Bg + d0));

#pragma unroll
    for (int i = 0; i < 8; i++) {
        int gnode = nodeBase + n0 + i;
        if (gnode >= n) break;
        float m0 = fmaxf(accP[i][0] + bm.x, 0.f);
        float m1 = fmaxf(accP[i][1] + bm.y, 0.f);
        float m2 = fmaxf(accP[i][2] + bm.z, 0.f);
        float m3 = fmaxf(accP[i][3] + bm.w, 0.f);
        float e0 = __expf(accG[i][0] + bg.x);
        float e1 = __expf(accG[i][1] + bg.y);
        float e2 = __expf(accG[i][2] + bg.z);
        float e3 = __expf(accG[i][3] + bg.w);
        uint4 v;
        v.x = h2_as_u32(__floats2half2_rn(e0, m0));   // low=GE, high=M
        v.y = h2_as_u32(__floats2half2_rn(e1, m1));
        v.z = h2_as_u32(__floats2half2_rn(e2, m2));
        v.w = h2_as_u32(__floats2half2_rn(e3, m3));
        g_comb[(size_t)gnode * 16 + dg] = v;
    }
}

// ---------------------------------------------------------------------------
// CSR build: histogram (vectorized) -> scan (3 kernels) -> scatter (vectorized)
// ---------------------------------------------------------------------------
__global__ void k_hist(const int* __restrict__ ridx, int E) {
    int i4 = blockIdx.x * blockDim.x + threadIdx.x;
    int base = i4 * 4;
    if (base + 3 < E) {
        int4 r = __ldg(reinterpret_cast<const int4*>(ridx) + i4);
        atomicAdd(&g_count[r.x], 1);
        atomicAdd(&g_count[r.y], 1);
        atomicAdd(&g_count[r.z], 1);
        atomicAdd(&g_count[r.w], 1);
    } else {
        for (int i = base; i < E; i++) atomicAdd(&g_count[__ldg(ridx + i)], 1);
    }
}

__global__ void __launch_bounds__(1024) k_scan1(int n) {
    __shared__ int sd[1024];
    int tid = threadIdx.x;
    int i = blockIdx.x * 1024 + tid;
    sd[tid] = (i < n) ? g_count[i] : 0;
    __syncthreads();
#pragma unroll
    for (int s = 512; s > 0; s >>= 1) {
        if (tid < s) sd[tid] += sd[tid + s];
        __syncthreads();
    }
    if (tid == 0) g_bsum[blockIdx.x] = sd[0];
}

__global__ void __launch_bounds__(1024) k_scan2(int nb, int n) {
    __shared__ int sd[1024];
    int tid = threadIdx.x;
    int v = (tid < nb) ? g_bsum[tid] : 0;
    sd[tid] = v;
    __syncthreads();
#pragma unroll
    for (int d = 1; d < 1024; d <<= 1) {
        int t = (tid >= d) ? sd[tid - d] : 0;
        __syncthreads();
        sd[tid] += t;
        __syncthreads();
    }
    if (tid < nb) g_bsum[tid] = sd[tid] - v;   // exclusive
    if (tid == 1023) g_rowstart[n] = sd[1023]; // total
}

__global__ void __launch_bounds__(1024) k_scan3(int n) {
    __shared__ int sd[1024];
    int tid = threadIdx.x;
    int i = blockIdx.x * 1024 + tid;
    int v = (i < n) ? g_count[i] : 0;
    sd[tid] = v;
    __syncthreads();
#pragma unroll
    for (int d = 1; d < 1024; d <<= 1) {
        int t = (tid >= d) ? sd[tid - d] : 0;
        __syncthreads();
        sd[tid] += t;
        __syncthreads();
    }
    if (i < n) {
        int excl = sd[tid] - v + g_bsum[blockIdx.x];
        g_rowstart[i] = excl;
        g_cursor[i] = excl;
    }
}

__global__ void k_scatter(const int* __restrict__ sidx, const int* __restrict__ ridx,
                          const int* __restrict__ tidx, int E) {
    int i4 = blockIdx.x * blockDim.x + threadIdx.x;
    int base = i4 * 4;
    if (base + 3 < E) {
        int4 s = __ldg(reinterpret_cast<const int4*>(sidx) + i4);
        int4 r = __ldg(reinterpret_cast<const int4*>(ridx) + i4);
        int4 t = __ldg(reinterpret_cast<const int4*>(tidx) + i4);
        int p0 = atomicAdd(&g_cursor[r.x], 1);
        int p1 = atomicAdd(&g_cursor[r.y], 1);
        int p2 = atomicAdd(&g_cursor[r.z], 1);
        int p3 = atomicAdd(&g_cursor[r.w], 1);
        g_csr[p0] = ((unsigned)s.x << 8) | (unsigned)t.x;
        g_csr[p1] = ((unsigned)s.y << 8) | (unsigned)t.y;
        g_csr[p2] = ((unsigned)s.z << 8) | (unsigned)t.z;
        g_csr[p3] = ((unsigned)s.w << 8) | (unsigned)t.w;
    } else {
        for (int i = base; i < E; i++) {
            int r = __ldg(ridx + i);
            int pos = atomicAdd(&g_cursor[r], 1);
            g_csr[pos] = ((unsigned)__ldg(sidx + i) << 8) | (unsigned)__ldg(tidx + i);
        }
    }
}

// ---------------------------------------------------------------------------
// Accumulate: one 16-lane group per receiver. fp16 gather (16 B/lane/edge),
// fp32 accumulation. t = GE*eg; den += t; num += M*t  (GE rounding cancels
// in num/den for dominant edges). Writes out directly; no atomics, no k_div.
// ---------------------------------------------------------------------------
__global__ void __launch_bounds__(256) k_accum(float* __restrict__ out, int n) {
    int gid = (blockIdx.x * 256 + threadIdx.x) >> 4;   // receiver
    if (gid >= n) return;                               // group-uniform
    int lane = threadIdx.x & 15;
    int gbase = (threadIdx.x & 31) & ~15;
    unsigned mask = 0xFFFFu << gbase;

    int beg = __ldg(&g_rowstart[gid]);
    int end = __ldg(&g_rowstart[gid + 1]);

    float4 num = make_float4(0.f, 0.f, 0.f, 0.f);
    float4 den = make_float4(0.f, 0.f, 0.f, 0.f);

    for (int chunk = beg; chunk < end; chunk += 16) {
        int m = end - chunk; if (m > 16) m = 16;
        unsigned pk = 0;
        if (chunk + lane < end) pk = __ldg(&g_csr[chunk + lane]);
        for (int j = 0; j < m; j++) {
            unsigned p = __shfl_sync(mask, pk, gbase + j);
            int s = p >> 8;
            int t = p & 255;
            uint4 raw = __ldg(&g_comb[(size_t)s * 16 + lane]);
            float4 g = __ldg(reinterpret_cast<const float4*>(g_eg2 + t * DD) + lane);
            float2 f0 = __half22float2(u32_as_h2(raw.x));  // {GE0, M0}
            float2 f1 = __half22float2(u32_as_h2(raw.y));
            float2 f2 = __half22float2(u32_as_h2(raw.z));
            float2 f3 = __half22float2(u32_as_h2(raw.w));
            float t0 = f0.x * g.x;  den.x += t0;  num.x = fmaf(f0.y, t0, num.x);
            float t1 = f1.x * g.y;  den.y += t1;  num.y = fmaf(f1.y, t1, num.y);
            float t2 = f2.x * g.z;  den.z += t2;  num.z = fmaf(f2.y, t2, num.z);
            float t3 = f3.x * g.w;  den.w += t3;  num.w = fmaf(f3.y, t3, num.w);
        }
    }

    float4 o;
    o.x = den.x > 0.f ? num.x / den.x : 0.f;
    o.y = den.y > 0.f ? num.y / den.y : 0.f;
    o.z = den.z > 0.f ? num.z / den.z : 0.f;
    o.w = den.w > 0.f ? num.w / den.w : 0.f;
    *(reinterpret_cast<float4*>(out + (size_t)gid * DD) + lane) = o;
}

// ---------------------------------------------------------------------------
extern "C" void kernel_launch(void* const* d_in, const int* in_sizes, int n_in,
                              void* d_out, int out_size)
{
    const float* X   = (const float*)d_in[0];
    const float* Vp  = (const float*)d_in[1];
    const float* Vg  = (const float*)d_in[2];
    const float* Eg  = (const float*)d_in[3];
    const float* Bm  = (const float*)d_in[4];
    const float* Bg  = (const float*)d_in[5];
    const int* sidx  = (const int*)d_in[6];
    const int* ridx  = (const int*)d_in[7];
    const int* tidx  = (const int*)d_in[8];
    float* out = (float*)d_out;

    int n        = in_sizes[0] / DD;
    int E        = in_sizes[6];
    int relTotal = in_sizes[3];
    int nb       = (n + 1023) / 1024;
    int e4       = (E + 3) / 4;

    k_init<<<(n + 255) / 256, 256>>>(Eg, n, relTotal);
    k_tables<<<(n + BN - 1) / BN, 256>>>(X, Vp, Vg, Bm, Bg, n);

    k_hist<<<(e4 + 255) / 256, 256>>>(ridx, E);
    k_scan1<<<nb, 1024>>>(n);
    k_scan2<<<1, 1024>>>(nb, n);
    k_scan3<<<nb, 1024>>>(n);
    k_scatter<<<(e4 + 255) / 256, 256>>>(sidx, ridx, tidx, E);

    long long work = (long long)n * 16;
    k_accum<<<(int)((work + 255) / 256), 256>>>(out, n);
}

// round 10
// speedup vs baseline: 1.1645x; 1.1533x over previous
#include <cuda_runtime.h>
#include <cuda_fp16.h>
#include <cstdint>

#define DD 64
#define NMAX 100032
#define NRELMAX 256
#define EMAX 2000000

// bit-cast helpers
__device__ __forceinline__ unsigned h2_as_u32(__half2 h) {
    union { __half2 h; unsigned u; } c; c.h = h; return c.u;
}
__device__ __forceinline__ __half2 u32_as_h2(unsigned u) {
    union { unsigned u; __half2 h; } c; c.u = u; return c.h;
}
__device__ __forceinline__ uint32_t cvt_tf32(float f) {
    uint32_t u;
    asm("cvt.rna.tf32.f32 %0, %1;" : "=r"(u) : "f"(f));
    return u;
}
// m16n8k8 tf32 MMA (sm_80+ PTX, no arch suffix -> legal on sm_100 target)
__device__ __forceinline__ void mma_t(float* d, uint32_t a0, uint32_t a1, uint32_t a2,
                                      uint32_t a3, uint32_t b0, uint32_t b1) {
    asm("mma.sync.aligned.m16n8k8.row.col.f32.tf32.tf32.f32 "
        "{%0,%1,%2,%3}, {%4,%5,%6,%7}, {%8,%9}, {%0,%1,%2,%3};"
        : "+f"(d[0]), "+f"(d[1]), "+f"(d[2]), "+f"(d[3])
        : "r"(a0), "r"(a1), "r"(a2), "r"(a3), "r"(b0), "r"(b1));
}

// Static scratch
// per node: 64 dims x half2{GE, M} = 256 B; viewed as u32[node][64]
__device__ uint4 g_comb[(size_t)NMAX * 16];
__device__ float g_eg2[NRELMAX * DD];
__device__ int   g_count[NMAX];
__device__ int   g_rowstart[NMAX + 1];
__device__ int   g_cursor[NMAX];
__device__ int   g_bsum[1024];
__device__ unsigned g_csr[EMAX];                      // packed (s<<8)|t

// ---------------------------------------------------------------------------
// init: zero degree counters + EG2 = exp(E_gate)
// ---------------------------------------------------------------------------
__global__ void k_init(const float* __restrict__ Eg, int n, int relTotal) {
    int i = blockIdx.x * blockDim.x + threadIdx.x;
    if (i < n) g_count[i] = 0;
    if (i < relTotal) g_eg2[i] = __expf(Eg[i]);
}

// ---------------------------------------------------------------------------
// k_tables via mma.sync tf32 (tensor pipe).
//   D[128 x 128] = Xtile[128 x 64] @ [Vp|Vg][64 x 128]
//   cols 0..63 -> P, cols 64..127 -> G
//   epilogue: M=relu(P+Bm), GE=exp(G+Bg), pack half2{GE,M} -> g_comb
// smem tiles padded to stride 68 floats: (4*row + col) mod 32 -> conflict-free
// fragment loads.
// ---------------------------------------------------------------------------
#define XS 68
#define SMX_BYTES (128 * XS * 4)
#define SM_TOTAL (2 * SMX_BYTES)

__global__ void __launch_bounds__(256) k_tables_mma(
    const float* __restrict__ X, const float* __restrict__ Vp,
    const float* __restrict__ Vg, const float* __restrict__ Bm,
    const float* __restrict__ Bg, int n)
{
    extern __shared__ float smf[];
    float* sX = smf;                 // [128][68]
    float* sW = smf + 128 * XS;      // [128][68]  (row n = column n of [Vp|Vg])
    int tid = threadIdx.x;
    int nodeBase = blockIdx.x * 128;

    // stage X tile (tf32-rounded)
    {
        const float4* g4 = reinterpret_cast<const float4*>(X);
        for (int i = tid; i < 128 * 16; i += 256) {
            int row = i >> 4, c4 = i & 15;
            float4 v = make_float4(0.f, 0.f, 0.f, 0.f);
            if (nodeBase + row < n) v = __ldg(g4 + (size_t)(nodeBase + row) * 16 + c4);
            float* dst = sX + row * XS + c4 * 4;
            dst[0] = __uint_as_float(cvt_tf32(v.x));
            dst[1] = __uint_as_float(cvt_tf32(v.y));
            dst[2] = __uint_as_float(cvt_tf32(v.z));
            dst[3] = __uint_as_float(cvt_tf32(v.w));
        }
    }
    // stage W transposed: sW[c][k] = Vp[k][c], sW[c+64][k] = Vg[k][c]
    for (int i = tid; i < 64 * 64; i += 256) {
        int k = i >> 6, c = i & 63;
        sW[c * XS + k]        = __uint_as_float(cvt_tf32(__ldg(Vp + i)));
        sW[(c + 64) * XS + k] = __uint_as_float(cvt_tf32(__ldg(Vg + i)));
    }
    __syncthreads();

    int wid = tid >> 5;
    int lane = tid & 31;
    int group = lane >> 2;    // 0..7
    int tig = lane & 3;       // 0..3
    int r0 = wid * 16 + group;       // warp covers rows wid*16..+15
    int r1 = r0 + 8;

    float acc[16][4];
#pragma unroll
    for (int j = 0; j < 16; j++)
#pragma unroll
        for (int q = 0; q < 4; q++) acc[j][q] = 0.f;

    const uint32_t* uX = reinterpret_cast<const uint32_t*>(sX);
    const uint32_t* uW = reinterpret_cast<const uint32_t*>(sW);

#pragma unroll
    for (int ks = 0; ks < 8; ks++) {
        int k0 = ks * 8;
        uint32_t a0 = uX[r0 * XS + k0 + tig];
        uint32_t a1 = uX[r1 * XS + k0 + tig];
        uint32_t a2 = uX[r0 * XS + k0 + tig + 4];
        uint32_t a3 = uX[r1 * XS + k0 + tig + 4];
#pragma unroll
        for (int nt = 0; nt < 16; nt++) {
            uint32_t b0 = uW[(nt * 8 + group) * XS + k0 + tig];
            uint32_t b1 = uW[(nt * 8 + group) * XS + k0 + tig + 4];
            mma_t(acc[nt], a0, a1, a2, a3, b0, b1);
        }
    }

    // epilogue: tile j (P) pairs with tile j+8 (G) on the same dims
    int gnode0 = nodeBase + r0;
    int gnode1 = nodeBase + r1;
    uint2* comb2 = reinterpret_cast<uint2*>(g_comb);

#pragma unroll
    for (int j = 0; j < 8; j++) {
        int d0 = j * 8 + 2 * tig;          // even dim
        int d1 = d0 + 1;
        float bm0 = __ldg(Bm + d0), bm1 = __ldg(Bm + d1);
        float bg0 = __ldg(Bg + d0), bg1 = __ldg(Bg + d1);
        if (gnode0 < n) {
            float m0 = fmaxf(acc[j][0] + bm0, 0.f);
            float m1 = fmaxf(acc[j][1] + bm1, 0.f);
            float e0 = __expf(acc[j + 8][0] + bg0);
            float e1 = __expf(acc[j + 8][1] + bg1);
            uint2 v;
            v.x = h2_as_u32(__floats2half2_rn(e0, m0));
            v.y = h2_as_u32(__floats2half2_rn(e1, m1));
            comb2[(size_t)gnode0 * 32 + (d0 >> 1)] = v;
        }
        if (gnode1 < n) {
            float m0 = fmaxf(acc[j][2] + bm0, 0.f);
            float m1 = fmaxf(acc[j][3] + bm1, 0.f);
            float e0 = __expf(acc[j + 8][2] + bg0);
            float e1 = __expf(acc[j + 8][3] + bg1);
            uint2 v;
            v.x = h2_as_u32(__floats2half2_rn(e0, m0));
            v.y = h2_as_u32(__floats2half2_rn(e1, m1));
            comb2[(size_t)gnode1 * 32 + (d0 >> 1)] = v;
        }
    }
}

// ---------------------------------------------------------------------------
// CSR build: histogram (vectorized) -> scan (3 kernels) -> scatter (vectorized)
// ---------------------------------------------------------------------------
__global__ void k_hist(const int* __restrict__ ridx, int E) {
    int i4 = blockIdx.x * blockDim.x + threadIdx.x;
    int base = i4 * 4;
    if (base + 3 < E) {
        int4 r = __ldg(reinterpret_cast<const int4*>(ridx) + i4);
        atomicAdd(&g_count[r.x], 1);
        atomicAdd(&g_count[r.y], 1);
        atomicAdd(&g_count[r.z], 1);
        atomicAdd(&g_count[r.w], 1);
    } else {
        for (int i = base; i < E; i++) atomicAdd(&g_count[__ldg(ridx + i)], 1);
    }
}

__global__ void __launch_bounds__(1024) k_scan1(int n) {
    __shared__ int sd[1024];
    int tid = threadIdx.x;
    int i = blockIdx.x * 1024 + tid;
    sd[tid] = (i < n) ? g_count[i] : 0;
    __syncthreads();
#pragma unroll
    for (int s = 512; s > 0; s >>= 1) {
        if (tid < s) sd[tid] += sd[tid + s];
        __syncthreads();
    }
    if (tid == 0) g_bsum[blockIdx.x] = sd[0];
}

__global__ void __launch_bounds__(1024) k_scan2(int nb, int n) {
    __shared__ int sd[1024];
    int tid = threadIdx.x;
    int v = (tid < nb) ? g_bsum[tid] : 0;
    sd[tid] = v;
    __syncthreads();
#pragma unroll
    for (int d = 1; d < 1024; d <<= 1) {
        int t = (tid >= d) ? sd[tid - d] : 0;
        __syncthreads();
        sd[tid] += t;
        __syncthreads();
    }
    if (tid < nb) g_bsum[tid] = sd[tid] - v;   // exclusive
    if (tid == 1023) g_rowstart[n] = sd[1023]; // total
}

__global__ void __launch_bounds__(1024) k_scan3(int n) {
    __shared__ int sd[1024];
    int tid = threadIdx.x;
    int i = blockIdx.x * 1024 + tid;
    int v = (i < n) ? g_count[i] : 0;
    sd[tid] = v;
    __syncthreads();
#pragma unroll
    for (int d = 1; d < 1024; d <<= 1) {
        int t = (tid >= d) ? sd[tid - d] : 0;
        __syncthreads();
        sd[tid] += t;
        __syncthreads();
    }
    if (i < n) {
        int excl = sd[tid] - v + g_bsum[blockIdx.x];
        g_rowstart[i] = excl;
        g_cursor[i] = excl;
    }
}

__global__ void k_scatter(const int* __restrict__ sidx, const int* __restrict__ ridx,
                          const int* __restrict__ tidx, int E) {
    int i4 = blockIdx.x * blockDim.x + threadIdx.x;
    int base = i4 * 4;
    if (base + 3 < E) {
        int4 s = __ldg(reinterpret_cast<const int4*>(sidx) + i4);
        int4 r = __ldg(reinterpret_cast<const int4*>(ridx) + i4);
        int4 t = __ldg(reinterpret_cast<const int4*>(tidx) + i4);
        int p0 = atomicAdd(&g_cursor[r.x], 1);
        int p1 = atomicAdd(&g_cursor[r.y], 1);
        int p2 = atomicAdd(&g_cursor[r.z], 1);
        int p3 = atomicAdd(&g_cursor[r.w], 1);
        g_csr[p0] = ((unsigned)s.x << 8) | (unsigned)t.x;
        g_csr[p1] = ((unsigned)s.y << 8) | (unsigned)t.y;
        g_csr[p2] = ((unsigned)s.z << 8) | (unsigned)t.z;
        g_csr[p3] = ((unsigned)s.w << 8) | (unsigned)t.w;
    } else {
        for (int i = base; i < E; i++) {
            int r = __ldg(ridx + i);
            int pos = atomicAdd(&g_cursor[r], 1);
            g_csr[pos] = ((unsigned)__ldg(sidx + i) << 8) | (unsigned)__ldg(tidx + i);
        }
    }
}

// ---------------------------------------------------------------------------
// Accumulate: one 16-lane group per receiver. fp16 gather, fp32 accumulation.
// ---------------------------------------------------------------------------
__global__ void __launch_bounds__(256) k_accum(float* __restrict__ out, int n) {
    int gid = (blockIdx.x * 256 + threadIdx.x) >> 4;   // receiver
    if (gid >= n) return;                               // group-uniform
    int lane = threadIdx.x & 15;
    int gbase = (threadIdx.x & 31) & ~15;
    unsigned mask = 0xFFFFu << gbase;

    int beg = __ldg(&g_rowstart[gid]);
    int end = __ldg(&g_rowstart[gid + 1]);

    float4 num = make_float4(0.f, 0.f, 0.f, 0.f);
    float4 den = make_float4(0.f, 0.f, 0.f, 0.f);

    for (int chunk = beg; chunk < end; chunk += 16) {
        int m = end - chunk; if (m > 16) m = 16;
        unsigned pk = 0;
        if (chunk + lane < end) pk = __ldg(&g_csr[chunk + lane]);
        for (int j = 0; j < m; j++) {
            unsigned p = __shfl_sync(mask, pk, gbase + j);
            int s = p >> 8;
            int t = p & 255;
            uint4 raw = __ldg(&g_comb[(size_t)s * 16 + lane]);
            float4 g = __ldg(reinterpret_cast<const float4*>(g_eg2 + t * DD) + lane);
            float2 f0 = __half22float2(u32_as_h2(raw.x));  // {GE0, M0}
            float2 f1 = __half22float2(u32_as_h2(raw.y));
            float2 f2 = __half22float2(u32_as_h2(raw.z));
            float2 f3 = __half22float2(u32_as_h2(raw.w));
            float t0 = f0.x * g.x;  den.x += t0;  num.x = fmaf(f0.y, t0, num.x);
            float t1 = f1.x * g.y;  den.y += t1;  num.y = fmaf(f1.y, t1, num.y);
            float t2 = f2.x * g.z;  den.z += t2;  num.z = fmaf(f2.y, t2, num.z);
            float t3 = f3.x * g.w;  den.w += t3;  num.w = fmaf(f3.y, t3, num.w);
        }
    }

    float4 o;
    o.x = den.x > 0.f ? num.x / den.x : 0.f;
    o.y = den.y > 0.f ? num.y / den.y : 0.f;
    o.z = den.z > 0.f ? num.z / den.z : 0.f;
    o.w = den.w > 0.f ? num.w / den.w : 0.f;
    *(reinterpret_cast<float4*>(out + (size_t)gid * DD) + lane) = o;
}

// ---------------------------------------------------------------------------
extern "C" void kernel_launch(void* const* d_in, const int* in_sizes, int n_in,
                              void* d_out, int out_size)
{
    const float* X   = (const float*)d_in[0];
    const float* Vp  = (const float*)d_in[1];
    const float* Vg  = (const float*)d_in[2];
    const float* Eg  = (const float*)d_in[3];
    const float* Bm  = (const float*)d_in[4];
    const float* Bg  = (const float*)d_in[5];
    const int* sidx  = (const int*)d_in[6];
    const int* ridx  = (const int*)d_in[7];
    const int* tidx  = (const int*)d_in[8];
    float* out = (float*)d_out;

    int n        = in_sizes[0] / DD;
    int E        = in_sizes[6];
    int relTotal = in_sizes[3];
    int nb       = (n + 1023) / 1024;
    int e4       = (E + 3) / 4;

    cudaFuncSetAttribute(k_tables_mma, cudaFuncAttributeMaxDynamicSharedMemorySize, SM_TOTAL);

    k_init<<<(n + 255) / 256, 256>>>(Eg, n, relTotal);
    k_tables_mma<<<(n + 127) / 128, 256, SM_TOTAL>>>(X, Vp, Vg, Bm, Bg, n);

    k_hist<<<(e4 + 255) / 256, 256>>>(ridx, E);
    k_scan1<<<nb, 1024>>>(n);
    k_scan2<<<1, 1024>>>(nb, n);
    k_scan3<<<nb, 1024>>>(n);
    k_scatter<<<(e4 + 255) / 256, 256>>>(sidx, ridx, tidx, E);

    long long work = (long long)n * 16;
    k_accum<<<(int)((work + 255) / 256), 256>>>(out, n);
}